// round 8
// baseline (speedup 1.0000x reference)
#include <cuda_runtime.h>
#include <cstdint>

#define TPC 4   // tokens per tile

// Int4-weight-only embedding gather — persistent grid-stride form.
//
// R4-R7 established: traffic is at the ~486MB floor and DRAM pins at ~73.5%
// of spec regardless of MLP depth (2/4/8) or occupancy (43-89%). Remaining
// untested term: wave-transition overhead. grid=16384 at occ 8 is ~14 waves;
// (n_waves-1)*T_wave_trans(~2360cyc) could expose a few us. This version
// launches exactly one wave (SMs * 8 CTAs) and grid-strides over tiles, and
// hoists the dtype probe out of the per-tile work (once per CTA).
//
// Index dtype (int64 vs int32) detected inline: lane L probes the high word
// of entry L under the int64 interpretation (same 256B region for every CTA
// -> L2 hot). int64 => all high words 0 (indices < 128000); int32 => random
// indices, P(all 32 == 0) ~ (1/128000)^32 ~ 0.
__global__ __launch_bounds__(256)
void int4_embedding_kernel(const int* __restrict__ x32,
                           const int4* __restrict__ weight,    // [V, 256] int4 vecs
                           const float* __restrict__ scale,    // [V, 32]
                           const int* __restrict__ zero_point, // [V, 32]
                           float4* __restrict__ out,           // [T, 256]
                           int n_tokens, int n_tiles)
{
    const int t = threadIdx.x;                          // 0..255
    const int lane = t & 31;

    // --- dtype probe: once per CTA ----------------------------------------
    const int hi_probe = (lane < n_tokens) ? __ldg(x32 + 2 * lane + 1) : 0;
    const bool is64 = (__ballot_sync(0xFFFFFFFFu, hi_probe != 0) == 0u);

    for (int tile = blockIdx.x; tile < n_tiles; tile += gridDim.x) {
        const long long base = (long long)tile * TPC;
        const int rem = (int)(n_tokens - base);
        const int nt = rem < TPC ? rem : TPC;

        // --- indices: lanes 0..TPC-1 load, shfl broadcasts -----------------
        int my = 0;
        if (lane < nt) {
            my = is64 ? __ldg(x32 + 2 * (base + lane))   // int64 low word
                      : __ldg(x32 + (base + lane));      // int32 value
        }
        int v[TPC];
        #pragma unroll
        for (int i = 0; i < TPC; ++i)
            v[i] = __shfl_sync(0xFFFFFFFFu, my, i);

        // --- weight loads: TPC independent 16B loads in flight -------------
        int4 w[TPC];
        #pragma unroll
        for (int i = 0; i < TPC; ++i)
            w[i] = __ldg(weight + (size_t)(unsigned)v[i] * 256 + t);

        const int g = t >> 3;                            // group = (4t)/32
        float s[TPC], z[TPC];
        #pragma unroll
        for (int i = 0; i < TPC; ++i) {
            const size_t srow = (size_t)(unsigned)v[i] * 32 + g;
            s[i] = __ldg(scale + srow);
            z[i] = (float)__ldg(zero_point + srow);
        }

        #pragma unroll
        for (int i = 0; i < TPC; ++i) {
            float4 o;
            o.x = ((float)w[i].x - z[i]) * s[i];
            o.y = ((float)w[i].y - z[i]) * s[i];
            o.z = ((float)w[i].z - z[i]) * s[i];
            o.w = ((float)w[i].w - z[i]) * s[i];
            if (i < nt) {
                // Streaming store: write-once output stays out of L2 so L2
                // capacity goes to weight-row reuse (duplicate indices).
                __stcs(out + (size_t)(base + i) * 256 + t, o);
            }
        }
    }
}

extern "C" void kernel_launch(void* const* d_in, const int* in_sizes, int n_in,
                              void* d_out, int out_size) {
    const int*   x      = (const int*)d_in[0];        // [32, 2048] int64 (or int32)
    const int4*  weight = (const int4*)d_in[1];       // [128000, 1024] int32
    const float* scale  = (const float*)d_in[2];      // [128000, 32] fp32
    const int*   zp     = (const int*)d_in[3];        // [128000, 32] int32
    float4*      out    = (float4*)d_out;             // [32, 2048, 1024] fp32

    const int n_tokens = in_sizes[0];                 // 65536
    const int n_tiles  = (n_tokens + TPC - 1) / TPC;  // 16384

    // One wave: SMs * 8 CTAs (regs=32, 256thr -> 8 CTAs/SM resident).
    static int n_sms = 0;
    if (n_sms == 0) cudaDeviceGetAttribute(&n_sms, cudaDevAttrMultiProcessorCount, 0);
    int grid = n_sms * 8;
    if (grid > n_tiles) grid = n_tiles;

    int4_embedding_kernel<<<grid, 256>>>(x, weight, scale, zp, out,
                                         n_tokens, n_tiles);
}

// round 9
// speedup vs baseline: 1.0963x; 1.0963x over previous
#include <cuda_runtime.h>
#include <cstdint>

#define TPC 4   // tokens per CTA

// Int4-weight-only embedding gather, HBM-roofline form. FINAL.
//
// Convergence evidence (R4-R8): traffic is at the ~486MB floor (268MB output
// write + ~205MB distinct weight rows + scale/zp) and DRAM pins at ~73.5% of
// spec — the mixed read/write random-row turnaround ceiling — across MLP
// depth 2/4/8, occupancy 43-97%, and persistent vs multi-wave launch (the
// persistent one-wave variant REGRESSED: grid-stride serializes tiles within
// a CTA and loses scheduler load-balancing). Best-measured config: one CTA
// per 4 tokens, 256 threads, default regalloc (high occupancy).
//
// Index dtype (int64 vs int32) detected inline with zero extra round-trips:
// lane L probes the high word of entry L under the int64 interpretation
// (same 256B region for every CTA -> L2 hot). int64 => all high words 0
// (indices < 128000); int32 => those words are random indices,
// P(all 32 == 0) ~ (1/128000)^32 ~ 0. This CTA's indices are loaded
// speculatively by lanes 0..TPC-1 in the same batch (both interpretations)
// and broadcast via shfl after one ballot — index resolution costs a single
// memory round-trip, fully overlapped.
__global__ __launch_bounds__(256)
void int4_embedding_kernel(const int* __restrict__ x32,
                           const int4* __restrict__ weight,    // [V, 256] int4 vecs
                           const float* __restrict__ scale,    // [V, 32]
                           const int* __restrict__ zero_point, // [V, 32]
                           float4* __restrict__ out,           // [T, 256]
                           int n_tokens)
{
    const int t = threadIdx.x;                          // 0..255
    const int lane = t & 31;
    const long long base = (long long)blockIdx.x * TPC;
    const int rem = (int)(n_tokens - base);
    const int nt = rem < TPC ? rem : TPC;

    // --- independent loads, all issued together ---------------------------
    const int hi_probe = (lane < n_tokens) ? __ldg(x32 + 2 * lane + 1) : 0;

    int my64 = 0, my32 = 0;
    if (lane < nt) {                                    // TPC <= 32
        my64 = __ldg(x32 + 2 * (base + lane));          // int64 low word
        my32 = __ldg(x32 + (base + lane));              // int32 value
    }

    // --- resolve dtype + broadcast indices --------------------------------
    const bool is64 = (__ballot_sync(0xFFFFFFFFu, hi_probe != 0) == 0u);
    const int mysel = is64 ? my64 : my32;

    int v[TPC];
    #pragma unroll
    for (int i = 0; i < TPC; ++i)
        v[i] = __shfl_sync(0xFFFFFFFFu, mysel, i);

    // --- weight loads: TPC independent 16B loads in flight ----------------
    int4 w[TPC];
    #pragma unroll
    for (int i = 0; i < TPC; ++i)
        w[i] = __ldg(weight + (size_t)(unsigned)v[i] * 256 + t);

    const int g = t >> 3;                                // group = (4t)/32
    float s[TPC], z[TPC];
    #pragma unroll
    for (int i = 0; i < TPC; ++i) {
        const size_t srow = (size_t)(unsigned)v[i] * 32 + g;
        s[i] = __ldg(scale + srow);
        z[i] = (float)__ldg(zero_point + srow);
    }

    #pragma unroll
    for (int i = 0; i < TPC; ++i) {
        float4 o;
        o.x = ((float)w[i].x - z[i]) * s[i];
        o.y = ((float)w[i].y - z[i]) * s[i];
        o.z = ((float)w[i].z - z[i]) * s[i];
        o.w = ((float)w[i].w - z[i]) * s[i];
        if (i < nt) {
            // Streaming store: write-once output stays out of L2 so L2
            // capacity goes to weight-row reuse (duplicate indices).
            __stcs(out + (size_t)(base + i) * 256 + t, o);
        }
    }
}

extern "C" void kernel_launch(void* const* d_in, const int* in_sizes, int n_in,
                              void* d_out, int out_size) {
    const int*   x      = (const int*)d_in[0];        // [32, 2048] int64 (or int32)
    const int4*  weight = (const int4*)d_in[1];       // [128000, 1024] int32
    const float* scale  = (const float*)d_in[2];      // [128000, 32] fp32
    const int*   zp     = (const int*)d_in[3];        // [128000, 32] int32
    float4*      out    = (float4*)d_out;             // [32, 2048, 1024] fp32

    const int n_tokens = in_sizes[0];                 // 65536

    const int grid = (n_tokens + TPC - 1) / TPC;
    int4_embedding_kernel<<<grid, 256>>>(x, weight, scale, zp, out, n_tokens);
}